// round 14
// baseline (speedup 1.0000x reference)
#include <cuda_runtime.h>
#include <cstdint>

#define NN   100000
#define NE   1600000
#define CIN  128
#define CH1  128
#define CH2  64
#define HALF (NN/2)
#define NB1  ((NN + 255) / 256)     // 391 scan blocks

// ---------------- scratch (static device globals; no allocs) ----------------
__device__ __align__(16) float g_xw1[(size_t)NN * CH1];   // x @ W1
__device__ __align__(16) float g_buf1[(size_t)NN * CH1];  // h1 = prelu(agg1)
__device__ __align__(16) float g_xw2[(size_t)NN * CH2];   // h1 @ W2
__device__ float              g_dinv1[NN];
__device__ float              g_dinv2[NN];
__device__ unsigned long long g_pk[NN];     // packed: wsum_fix [0:40) | et_sum [40:52) | cnt [52:64)
__device__ unsigned short     g_kloc[NE];   // per-edge local index within its dst
__device__ int   g_rowptr[NN + 1];          // CSR row pointers
__device__ int   g_psum[NB1];               // block partial sums for scan
__device__ __align__(16) int4 g_rec[NE];    // {src, c1_bits, c2_bits, 0} sorted by dst

// ---------------- side stream + events: lazily created on first call ----------
static cudaStream_t g_s2     = nullptr;
static cudaEvent_t  g_evFork = nullptr;
static cudaEvent_t  g_evJoin = nullptr;

// ---------------- f32x2 packed math helpers ----------------
__device__ __forceinline__ unsigned long long pack2(float x, float y) {
    unsigned long long r;
    asm("mov.b64 %0, {%1, %2};" : "=l"(r) : "f"(x), "f"(y));
    return r;
}
__device__ __forceinline__ void ffma2(unsigned long long& d,
                                      unsigned long long a, unsigned long long b) {
    asm("fma.rn.f32x2 %0, %1, %2, %3;" : "=l"(d) : "l"(a), "l"(b), "l"(d));
}
__device__ __forceinline__ float2 unpack2(unsigned long long v) {
    float2 f;
    asm("mov.b64 {%0, %1}, %2;" : "=f"(f.x), "=f"(f.y) : "l"(v));
    return f;
}

// ---------------- prep: init / packed histogram ----------------
__global__ __launch_bounds__(256) void k_init() {
    int i = blockIdx.x * 256 + threadIdx.x;
    if (i < NN) g_pk[i] = 0ULL;
}

__global__ __launch_bounds__(256) void k_pass1(const int* __restrict__ ei,
                                               const float* __restrict__ w,
                                               const int* __restrict__ et) {
    int e = blockIdx.x * 256 + threadIdx.x;
    if (e >= NE) return;
    int d = ei[NE + e];
    unsigned wfix = __float2uint_rn(w[e] * 16777216.0f);     // w in [0,1) -> < 2^24
    unsigned long long val = (unsigned long long)wfix
                           | ((unsigned long long)(unsigned)et[e] << 40)
                           | (1ULL << 52);
    unsigned long long old = atomicAdd(&g_pk[d], val);
    g_kloc[e] = (unsigned short)(old >> 52);                 // local index within dst
}

// ---------------- 3-kernel exclusive scan of counts -> g_rowptr ----------------
__global__ __launch_bounds__(256) void k_scan1() {
    __shared__ int s[256];
    int tid = threadIdx.x;
    int i = blockIdx.x * 256 + tid;
    int v = (i < NN) ? (int)(g_pk[i] >> 52) : 0;
    s[tid] = v;
    __syncthreads();
    for (int off = 1; off < 256; off <<= 1) {
        int t = (tid >= off) ? s[tid - off] : 0;
        __syncthreads();
        s[tid] += t;
        __syncthreads();
    }
    if (i < NN) g_rowptr[i] = s[tid] - v;   // block-local exclusive
    if (tid == 255) g_psum[blockIdx.x] = s[255];
}

__global__ __launch_bounds__(512) void k_scan2() {
    __shared__ int s[512];
    int tid = threadIdx.x;
    int v = (tid < NB1) ? g_psum[tid] : 0;
    s[tid] = v;
    __syncthreads();
    for (int off = 1; off < 512; off <<= 1) {
        int t = (tid >= off) ? s[tid - off] : 0;
        __syncthreads();
        s[tid] += t;
        __syncthreads();
    }
    if (tid < NB1) g_psum[tid] = s[tid] - v;   // exclusive over blocks
}

__global__ __launch_bounds__(256) void k_scan3() {      // + fused rsqrt of degrees
    int i = blockIdx.x * 256 + threadIdx.x;
    if (i < NN) {
        g_rowptr[i] += g_psum[blockIdx.x];
        unsigned long long pk = g_pk[i];
        float wsum = (float)(pk & 0xFFFFFFFFFFULL) * (1.0f / 16777216.0f);
        float ets  = (float)((pk >> 40) & 0xFFFu);
        g_dinv1[i] = rsqrtf(wsum + 1.0f);                 // + self loop
        g_dinv2[i] = rsqrtf(ets + 1.0f);
    }
    if (i == 0) g_rowptr[NN] = NE;
}

// ---------------- reorder edges into dst-sorted records (NO atomics) --------
__global__ __launch_bounds__(256) void k_reorder(const int* __restrict__ ei,
                                                 const float* __restrict__ w,
                                                 const int* __restrict__ et) {
    int e = blockIdx.x * 256 + threadIdx.x;
    if (e >= NE) return;
    int s = ei[e];
    int d = ei[NE + e];
    int pos = g_rowptr[d] + (int)g_kloc[e];
    float c1 = g_dinv1[s] * w[e] * g_dinv1[d];
    float c2 = g_dinv2[s] * (float)et[e] * g_dinv2[d];
    g_rec[pos] = make_int4(s, __float_as_int(c1), __float_as_int(c2), 0);
}

// ---------------- GEMM: Y[nrows,COUT] = X[nrows,CIN] @ W[CIN,COUT] ----------------
template<int COUT>
__global__ __launch_bounds__(256)
void k_gemm(const float* __restrict__ X, const float* __restrict__ W,
            float* __restrict__ Y, int nrows) {
    constexpr int TC = 8, TR = 8, KC = 32;
    constexpr int CG = COUT / TC;
    constexpr int RG = 256 / CG;
    constexpr int RT = RG * TR;
    __shared__ float sX[RT][KC];
    __shared__ float sW[KC][COUT];

    int tid = threadIdx.x;
    int tx = tid % CG, ty = tid / CG;
    int r0base = blockIdx.x * RT;
    int r0 = ty * TR;

    unsigned long long acc[TR][4];
    #pragma unroll
    for (int j = 0; j < TR; j++) {
        acc[j][0] = 0ULL; acc[j][1] = 0ULL; acc[j][2] = 0ULL; acc[j][3] = 0ULL;
    }

    for (int k0 = 0; k0 < CIN; k0 += KC) {
        #pragma unroll
        for (int idx = tid; idx < RT * (KC / 4); idx += 256) {
            int row = idx / (KC / 4);
            int kq  = idx % (KC / 4);
            int grow = r0base + row;
            float4 v = (grow < nrows)
                ? ((const float4*)(X + (size_t)grow * CIN + k0))[kq]
                : make_float4(0.f, 0.f, 0.f, 0.f);
            *(float4*)&sX[row][kq * 4] = v;
        }
        #pragma unroll
        for (int idx = tid; idx < KC * (COUT / 4); idx += 256) {
            int kk = idx / (COUT / 4);
            int cq = idx % (COUT / 4);
            *(float4*)&sW[kk][cq * 4] = ((const float4*)(W + (size_t)(k0 + kk) * COUT))[cq];
        }
        __syncthreads();

        #pragma unroll 4
        for (int kk = 0; kk < KC; kk++) {
            ulonglong2 w01 = *(const ulonglong2*)&sW[kk][tx * TC];
            ulonglong2 w23 = *(const ulonglong2*)&sW[kk][tx * TC + 4];
            #pragma unroll
            for (int j = 0; j < TR; j++) {
                float xv = sX[r0 + j][kk];
                unsigned long long xx = pack2(xv, xv);
                ffma2(acc[j][0], xx, w01.x);
                ffma2(acc[j][1], xx, w01.y);
                ffma2(acc[j][2], xx, w23.x);
                ffma2(acc[j][3], xx, w23.y);
            }
        }
        __syncthreads();
    }

    #pragma unroll
    for (int j = 0; j < TR; j++) {
        int grow = r0base + r0 + j;
        if (grow < nrows) {
            float2 p0 = unpack2(acc[j][0]);
            float2 p1 = unpack2(acc[j][1]);
            float2 p2 = unpack2(acc[j][2]);
            float2 p3 = unpack2(acc[j][3]);
            float4* yp = (float4*)(Y + (size_t)grow * COUT + tx * TC);
            yp[0] = make_float4(p0.x, p0.y, p1.x, p1.y);
            yp[1] = make_float4(p2.x, p2.y, p3.x, p3.y);
        }
    }
}

// ---------------- layer-1 aggregation: warp per dst, smem-staged records ----------------
__global__ __launch_bounds__(256)
void k_agg1(const float* __restrict__ xw, const float* __restrict__ b,
            const float* __restrict__ a, float* __restrict__ outbuf) {
    __shared__ int4 srec[8][32];
    int wq   = threadIdx.x >> 5;
    int lane = threadIdx.x & 31;
    int dst  = blockIdx.x * 8 + wq;
    if (dst >= NN) return;

    const float4* xw4 = (const float4*)xw;
    float dv = g_dinv1[dst];
    float4 acc = xw4[(size_t)dst * 32 + lane];
    float sc = dv * dv;
    acc.x *= sc; acc.y *= sc; acc.z *= sc; acc.w *= sc;

    int start = g_rowptr[dst], end = g_rowptr[dst + 1];
    for (int base = start; base < end; base += 32) {
        int n = end - base; if (n > 32) n = 32;
        if (lane < n) srec[wq][lane] = g_rec[base + lane];
        __syncwarp();
        int j = 0;
        for (; j + 4 <= n; j += 4) {
            int4 r0 = srec[wq][j], r1 = srec[wq][j + 1];
            int4 r2 = srec[wq][j + 2], r3 = srec[wq][j + 3];
            float4 v0 = xw4[(size_t)r0.x * 32 + lane];
            float4 v1 = xw4[(size_t)r1.x * 32 + lane];
            float4 v2 = xw4[(size_t)r2.x * 32 + lane];
            float4 v3 = xw4[(size_t)r3.x * 32 + lane];
            float c0 = __int_as_float(r0.y), c1 = __int_as_float(r1.y);
            float c2 = __int_as_float(r2.y), c3 = __int_as_float(r3.y);
            acc.x += c0 * v0.x; acc.y += c0 * v0.y; acc.z += c0 * v0.z; acc.w += c0 * v0.w;
            acc.x += c1 * v1.x; acc.y += c1 * v1.y; acc.z += c1 * v1.z; acc.w += c1 * v1.w;
            acc.x += c2 * v2.x; acc.y += c2 * v2.y; acc.z += c2 * v2.z; acc.w += c2 * v2.w;
            acc.x += c3 * v3.x; acc.y += c3 * v3.y; acc.z += c3 * v3.z; acc.w += c3 * v3.w;
        }
        for (; j < n; j++) {
            int4 r = srec[wq][j];
            float c = __int_as_float(r.y);
            float4 v = xw4[(size_t)r.x * 32 + lane];
            acc.x += c * v.x; acc.y += c * v.y; acc.z += c * v.z; acc.w += c * v.w;
        }
        __syncwarp();
    }

    float4 bb = ((const float4*)b)[lane];
    float4 aa = ((const float4*)a)[lane];
    acc.x += bb.x; acc.y += bb.y; acc.z += bb.z; acc.w += bb.w;
    acc.x = (acc.x >= 0.f) ? acc.x : aa.x * acc.x;
    acc.y = (acc.y >= 0.f) ? acc.y : aa.y * acc.y;
    acc.z = (acc.z >= 0.f) ? acc.z : aa.z * acc.z;
    acc.w = (acc.w >= 0.f) ? acc.w : aa.w * acc.w;
    ((float4*)outbuf)[(size_t)dst * 32 + lane] = acc;
}

// ---------------- layer-2 aggregation fused with epilogue ----------------
__device__ __forceinline__ float2 agg2_node(const float2* __restrict__ xw2,
                                            int4 (*srec)[32], int wq, int lane,
                                            int dst) {
    float dv = g_dinv2[dst];
    float2 acc = xw2[(size_t)dst * 32 + lane];
    float sc = dv * dv;
    acc.x *= sc; acc.y *= sc;

    int start = g_rowptr[dst], end = g_rowptr[dst + 1];
    for (int base = start; base < end; base += 32) {
        int n = end - base; if (n > 32) n = 32;
        if (lane < n) srec[wq][lane] = g_rec[base + lane];
        __syncwarp();
        int j = 0;
        for (; j + 4 <= n; j += 4) {
            int4 r0 = srec[wq][j], r1 = srec[wq][j + 1];
            int4 r2 = srec[wq][j + 2], r3 = srec[wq][j + 3];
            float c0 = __int_as_float(r0.z), c1 = __int_as_float(r1.z);
            float c2 = __int_as_float(r2.z), c3 = __int_as_float(r3.z);
            if (c0 != 0.f) { float2 v = xw2[(size_t)r0.x * 32 + lane]; acc.x += c0 * v.x; acc.y += c0 * v.y; }
            if (c1 != 0.f) { float2 v = xw2[(size_t)r1.x * 32 + lane]; acc.x += c1 * v.x; acc.y += c1 * v.y; }
            if (c2 != 0.f) { float2 v = xw2[(size_t)r2.x * 32 + lane]; acc.x += c2 * v.x; acc.y += c2 * v.y; }
            if (c3 != 0.f) { float2 v = xw2[(size_t)r3.x * 32 + lane]; acc.x += c3 * v.x; acc.y += c3 * v.y; }
        }
        for (; j < n; j++) {
            int4 r = srec[wq][j];
            float c = __int_as_float(r.z);
            if (c != 0.f) { float2 v = xw2[(size_t)r.x * 32 + lane]; acc.x += c * v.x; acc.y += c * v.y; }
        }
        __syncwarp();
    }
    return acc;
}

__global__ __launch_bounds__(256)
void k_agg2f(const float* __restrict__ xw, const float* __restrict__ b,
             const float* __restrict__ a, float* __restrict__ out) {
    __shared__ int4 srec[8][32];
    int wq   = threadIdx.x >> 5;
    int lane = threadIdx.x & 31;
    int node = blockIdx.x * 8 + wq;
    if (node >= HALF) return;

    const float2* xw2 = (const float2*)xw;
    float2 r1 = agg2_node(xw2, srec, wq, lane, node);
    float2 r2 = agg2_node(xw2, srec, wq, lane, node + HALF);

    float2 bb = ((const float2*)b)[lane];
    float2 aa = ((const float2*)a)[lane];
    r1.x += bb.x; r1.y += bb.y;
    r2.x += bb.x; r2.y += bb.y;
    r1.x = (r1.x >= 0.f) ? r1.x : aa.x * r1.x;
    r1.y = (r1.y >= 0.f) ? r1.y : aa.y * r1.y;
    r2.x = (r2.x >= 0.f) ? r2.x : aa.x * r2.x;
    r2.y = (r2.y >= 0.f) ? r2.y : aa.y * r2.y;
    float2 o = make_float2(0.5f * (r1.x + r2.x), 0.5f * (r1.y + r2.y));
    ((float2*)out)[(size_t)node * 32 + lane] = o;
}

// ---------------- launch ----------------
extern "C" void kernel_launch(void* const* d_in, const int* in_sizes, int n_in,
                              void* d_out, int out_size) {
    const float* x   = (const float*)d_in[0];
    const int*   ei  = (const int*)d_in[1];    // int32 (JAX x64 disabled)
    const float* ew  = (const float*)d_in[2];
    const int*   et  = (const int*)d_in[3];    // int32
    const float* W1  = (const float*)d_in[4];
    const float* b1  = (const float*)d_in[5];
    const float* a1  = (const float*)d_in[6];
    const float* W2  = (const float*)d_in[7];
    const float* b2  = (const float*)d_in[8];
    const float* a2  = (const float*)d_in[9];
    float* out = (float*)d_out;

    if (!g_s2) {
        cudaStreamCreateWithFlags(&g_s2, cudaStreamNonBlocking);
        cudaEventCreateWithFlags(&g_evFork, cudaEventDisableTiming);
        cudaEventCreateWithFlags(&g_evJoin, cudaEventDisableTiming);
    }

    float *xw1, *buf1, *xw2;
    cudaGetSymbolAddress((void**)&xw1,  g_xw1);
    cudaGetSymbolAddress((void**)&buf1, g_buf1);
    cudaGetSymbolAddress((void**)&xw2,  g_xw2);

    const int nodeGrid = (NN + 255) / 256;
    const int edgeGrid = (NE + 255) / 256;
    const int aggGrid  = (NN + 7) / 8;
    const int agg2Grid = (HALF + 7) / 8;

    // ---- fork: GEMM1 on side stream, concurrent with the CSR build ----
    cudaEventRecord(g_evFork, 0);
    cudaStreamWaitEvent(g_s2, g_evFork, 0);
    k_gemm<CH1><<<(NN + 127) / 128, 256, 0, g_s2>>>(x, W1, xw1, NN);
    cudaEventRecord(g_evJoin, g_s2);

    // ---- CSR build + norm coefficients (default stream) ----
    k_init<<<nodeGrid, 256>>>();
    k_pass1<<<edgeGrid, 256>>>(ei, ew, et);
    k_scan1<<<NB1, 256>>>();
    k_scan2<<<1, 512>>>();
    k_scan3<<<NB1, 256>>>();
    k_reorder<<<edgeGrid, 256>>>(ei, ew, et);

    // ---- join: agg1 needs both xw1 (side stream) and CSR (default) ----
    cudaStreamWaitEvent(0, g_evJoin, 0);
    k_agg1<<<aggGrid, 256>>>(xw1, b1, a1, buf1);

    // layer 2
    k_gemm<CH2><<<(NN + 255) / 256, 256>>>(buf1, W2, xw2, NN);
    k_agg2f<<<agg2Grid, 256>>>(xw2, b2, a2, out);
}

// round 15
// speedup vs baseline: 1.4892x; 1.4892x over previous
#include <cuda_runtime.h>
#include <cstdint>

#define NN   100000
#define NE   1600000
#define CIN  128
#define CH1  128
#define CH2  64
#define HALF (NN/2)
#define NB1  ((NN + 255) / 256)     // 391 scan blocks

// ---------------- scratch (static device globals; no allocs) ----------------
__device__ __align__(16) float g_xw1[(size_t)NN * CH1];   // x @ W1
__device__ __align__(16) float g_buf1[(size_t)NN * CH1];  // h1 = prelu(agg1)
__device__ __align__(16) float g_xw2[(size_t)NN * CH2];   // h1 @ W2
__device__ float          g_dinv1[NN];
__device__ float          g_dinv2[NN];
__device__ unsigned int   g_pk[NN];         // packed: cnt (low 16) | et_sum (high 16)
__device__ float          g_wsum[NN];       // sum of edge weights per dst
__device__ unsigned short g_kloc[NE];       // per-edge local index within its dst
__device__ int   g_rowptr[NN + 1];          // CSR row pointers
__device__ int   g_psum[NB1];               // block partial sums for scan
__device__ __align__(16) int4 g_rec[NE];    // {src, c1_bits, c2_bits, 0} sorted by dst

// ---------------- side stream + events: lazily created on first call ----------
static cudaStream_t g_s2     = nullptr;
static cudaEvent_t  g_evFork = nullptr;
static cudaEvent_t  g_evJoin = nullptr;

// ---------------- f32x2 packed math helpers ----------------
__device__ __forceinline__ unsigned long long pack2(float x, float y) {
    unsigned long long r;
    asm("mov.b64 %0, {%1, %2};" : "=l"(r) : "f"(x), "f"(y));
    return r;
}
__device__ __forceinline__ void ffma2(unsigned long long& d,
                                      unsigned long long a, unsigned long long b) {
    asm("fma.rn.f32x2 %0, %1, %2, %3;" : "=l"(d) : "l"(a), "l"(b), "l"(d));
}
__device__ __forceinline__ float2 unpack2(unsigned long long v) {
    float2 f;
    asm("mov.b64 {%0, %1}, %2;" : "=f"(f.x), "=f"(f.y) : "l"(v));
    return f;
}

// ---------------- prep: init / histogram ----------------
__global__ __launch_bounds__(256) void k_init() {
    int i = blockIdx.x * 256 + threadIdx.x;
    if (i < NN) { g_pk[i] = 0u; g_wsum[i] = 0.f; }
}

__global__ __launch_bounds__(256) void k_pass1(const int* __restrict__ ei,
                                               const float* __restrict__ w,
                                               const int* __restrict__ et) {
    int e = blockIdx.x * 256 + threadIdx.x;
    if (e >= NE) return;
    int d = ei[NE + e];
    unsigned old = atomicAdd(&g_pk[d], 1u | ((unsigned)et[e] << 16));
    g_kloc[e] = (unsigned short)(old & 0xFFFFu);   // local index within dst
    atomicAdd(&g_wsum[d], w[e]);
}

// ---------------- 3-kernel exclusive scan of counts -> g_rowptr ----------------
__global__ __launch_bounds__(256) void k_scan1() {
    __shared__ int s[256];
    int tid = threadIdx.x;
    int i = blockIdx.x * 256 + tid;
    int v = (i < NN) ? (int)(g_pk[i] & 0xFFFFu) : 0;
    s[tid] = v;
    __syncthreads();
    for (int off = 1; off < 256; off <<= 1) {
        int t = (tid >= off) ? s[tid - off] : 0;
        __syncthreads();
        s[tid] += t;
        __syncthreads();
    }
    if (i < NN) g_rowptr[i] = s[tid] - v;   // block-local exclusive
    if (tid == 255) g_psum[blockIdx.x] = s[255];
}

__global__ __launch_bounds__(512) void k_scan2() {
    __shared__ int s[512];
    int tid = threadIdx.x;
    int v = (tid < NB1) ? g_psum[tid] : 0;
    s[tid] = v;
    __syncthreads();
    for (int off = 1; off < 512; off <<= 1) {
        int t = (tid >= off) ? s[tid - off] : 0;
        __syncthreads();
        s[tid] += t;
        __syncthreads();
    }
    if (tid < NB1) g_psum[tid] = s[tid] - v;   // exclusive over blocks
}

__global__ __launch_bounds__(256) void k_scan3() {      // + fused rsqrt of degrees
    int i = blockIdx.x * 256 + threadIdx.x;
    if (i < NN) {
        g_rowptr[i] += g_psum[blockIdx.x];
        g_dinv1[i] = rsqrtf(g_wsum[i] + 1.0f);                    // + self loop
        g_dinv2[i] = rsqrtf((float)(g_pk[i] >> 16) + 1.0f);
    }
    if (i == 0) g_rowptr[NN] = NE;
}

// ---------------- reorder edges into dst-sorted records (NO atomics) --------
__global__ __launch_bounds__(256) void k_reorder(const int* __restrict__ ei,
                                                 const float* __restrict__ w,
                                                 const int* __restrict__ et) {
    int e = blockIdx.x * 256 + threadIdx.x;
    if (e >= NE) return;
    int s = ei[e];
    int d = ei[NE + e];
    int pos = g_rowptr[d] + (int)g_kloc[e];
    float c1 = g_dinv1[s] * w[e] * g_dinv1[d];
    float c2 = g_dinv2[s] * (float)et[e] * g_dinv2[d];
    g_rec[pos] = make_int4(s, __float_as_int(c1), __float_as_int(c2), 0);
}

// ---------------- GEMM: Y[nrows,COUT] = X[nrows,CIN] @ W[CIN,COUT] ----------------
template<int COUT>
__global__ __launch_bounds__(256)
void k_gemm(const float* __restrict__ X, const float* __restrict__ W,
            float* __restrict__ Y, int nrows) {
    constexpr int TC = 8, TR = 8, KC = 32;
    constexpr int CG = COUT / TC;
    constexpr int RG = 256 / CG;
    constexpr int RT = RG * TR;
    __shared__ float sX[RT][KC];
    __shared__ float sW[KC][COUT];

    int tid = threadIdx.x;
    int tx = tid % CG, ty = tid / CG;
    int r0base = blockIdx.x * RT;
    int r0 = ty * TR;

    unsigned long long acc[TR][4];
    #pragma unroll
    for (int j = 0; j < TR; j++) {
        acc[j][0] = 0ULL; acc[j][1] = 0ULL; acc[j][2] = 0ULL; acc[j][3] = 0ULL;
    }

    for (int k0 = 0; k0 < CIN; k0 += KC) {
        #pragma unroll
        for (int idx = tid; idx < RT * (KC / 4); idx += 256) {
            int row = idx / (KC / 4);
            int kq  = idx % (KC / 4);
            int grow = r0base + row;
            float4 v = (grow < nrows)
                ? ((const float4*)(X + (size_t)grow * CIN + k0))[kq]
                : make_float4(0.f, 0.f, 0.f, 0.f);
            *(float4*)&sX[row][kq * 4] = v;
        }
        #pragma unroll
        for (int idx = tid; idx < KC * (COUT / 4); idx += 256) {
            int kk = idx / (COUT / 4);
            int cq = idx % (COUT / 4);
            *(float4*)&sW[kk][cq * 4] = ((const float4*)(W + (size_t)(k0 + kk) * COUT))[cq];
        }
        __syncthreads();

        #pragma unroll 4
        for (int kk = 0; kk < KC; kk++) {
            ulonglong2 w01 = *(const ulonglong2*)&sW[kk][tx * TC];
            ulonglong2 w23 = *(const ulonglong2*)&sW[kk][tx * TC + 4];
            #pragma unroll
            for (int j = 0; j < TR; j++) {
                float xv = sX[r0 + j][kk];
                unsigned long long xx = pack2(xv, xv);
                ffma2(acc[j][0], xx, w01.x);
                ffma2(acc[j][1], xx, w01.y);
                ffma2(acc[j][2], xx, w23.x);
                ffma2(acc[j][3], xx, w23.y);
            }
        }
        __syncthreads();
    }

    #pragma unroll
    for (int j = 0; j < TR; j++) {
        int grow = r0base + r0 + j;
        if (grow < nrows) {
            float2 p0 = unpack2(acc[j][0]);
            float2 p1 = unpack2(acc[j][1]);
            float2 p2 = unpack2(acc[j][2]);
            float2 p3 = unpack2(acc[j][3]);
            float4* yp = (float4*)(Y + (size_t)grow * COUT + tx * TC);
            yp[0] = make_float4(p0.x, p0.y, p1.x, p1.y);
            yp[1] = make_float4(p2.x, p2.y, p3.x, p3.y);
        }
    }
}

// ---------------- layer-1 aggregation: warp per dst, smem-staged records ----------------
__global__ __launch_bounds__(256)
void k_agg1(const float* __restrict__ xw, const float* __restrict__ b,
            const float* __restrict__ a, float* __restrict__ outbuf) {
    __shared__ int4 srec[8][32];
    int wq   = threadIdx.x >> 5;
    int lane = threadIdx.x & 31;
    int dst  = blockIdx.x * 8 + wq;
    if (dst >= NN) return;

    const float4* xw4 = (const float4*)xw;
    float dv = g_dinv1[dst];
    float4 acc = xw4[(size_t)dst * 32 + lane];
    float sc = dv * dv;
    acc.x *= sc; acc.y *= sc; acc.z *= sc; acc.w *= sc;

    int start = g_rowptr[dst], end = g_rowptr[dst + 1];
    for (int base = start; base < end; base += 32) {
        int n = end - base; if (n > 32) n = 32;
        if (lane < n) srec[wq][lane] = g_rec[base + lane];
        __syncwarp();
        int j = 0;
        for (; j + 4 <= n; j += 4) {
            int4 r0 = srec[wq][j], r1 = srec[wq][j + 1];
            int4 r2 = srec[wq][j + 2], r3 = srec[wq][j + 3];
            float4 v0 = xw4[(size_t)r0.x * 32 + lane];
            float4 v1 = xw4[(size_t)r1.x * 32 + lane];
            float4 v2 = xw4[(size_t)r2.x * 32 + lane];
            float4 v3 = xw4[(size_t)r3.x * 32 + lane];
            float c0 = __int_as_float(r0.y), c1 = __int_as_float(r1.y);
            float c2 = __int_as_float(r2.y), c3 = __int_as_float(r3.y);
            acc.x += c0 * v0.x; acc.y += c0 * v0.y; acc.z += c0 * v0.z; acc.w += c0 * v0.w;
            acc.x += c1 * v1.x; acc.y += c1 * v1.y; acc.z += c1 * v1.z; acc.w += c1 * v1.w;
            acc.x += c2 * v2.x; acc.y += c2 * v2.y; acc.z += c2 * v2.z; acc.w += c2 * v2.w;
            acc.x += c3 * v3.x; acc.y += c3 * v3.y; acc.z += c3 * v3.z; acc.w += c3 * v3.w;
        }
        for (; j < n; j++) {
            int4 r = srec[wq][j];
            float c = __int_as_float(r.y);
            float4 v = xw4[(size_t)r.x * 32 + lane];
            acc.x += c * v.x; acc.y += c * v.y; acc.z += c * v.z; acc.w += c * v.w;
        }
        __syncwarp();
    }

    float4 bb = ((const float4*)b)[lane];
    float4 aa = ((const float4*)a)[lane];
    acc.x += bb.x; acc.y += bb.y; acc.z += bb.z; acc.w += bb.w;
    acc.x = (acc.x >= 0.f) ? acc.x : aa.x * acc.x;
    acc.y = (acc.y >= 0.f) ? acc.y : aa.y * acc.y;
    acc.z = (acc.z >= 0.f) ? acc.z : aa.z * acc.z;
    acc.w = (acc.w >= 0.f) ? acc.w : aa.w * acc.w;
    ((float4*)outbuf)[(size_t)dst * 32 + lane] = acc;
}

// ---------------- layer-2 aggregation fused with epilogue ----------------
__device__ __forceinline__ float2 agg2_node(const float2* __restrict__ xw2,
                                            int4 (*srec)[32], int wq, int lane,
                                            int dst) {
    float dv = g_dinv2[dst];
    float2 acc = xw2[(size_t)dst * 32 + lane];
    float sc = dv * dv;
    acc.x *= sc; acc.y *= sc;

    int start = g_rowptr[dst], end = g_rowptr[dst + 1];
    for (int base = start; base < end; base += 32) {
        int n = end - base; if (n > 32) n = 32;
        if (lane < n) srec[wq][lane] = g_rec[base + lane];
        __syncwarp();
        int j = 0;
        for (; j + 4 <= n; j += 4) {
            int4 r0 = srec[wq][j], r1 = srec[wq][j + 1];
            int4 r2 = srec[wq][j + 2], r3 = srec[wq][j + 3];
            float c0 = __int_as_float(r0.z), c1 = __int_as_float(r1.z);
            float c2 = __int_as_float(r2.z), c3 = __int_as_float(r3.z);
            if (c0 != 0.f) { float2 v = xw2[(size_t)r0.x * 32 + lane]; acc.x += c0 * v.x; acc.y += c0 * v.y; }
            if (c1 != 0.f) { float2 v = xw2[(size_t)r1.x * 32 + lane]; acc.x += c1 * v.x; acc.y += c1 * v.y; }
            if (c2 != 0.f) { float2 v = xw2[(size_t)r2.x * 32 + lane]; acc.x += c2 * v.x; acc.y += c2 * v.y; }
            if (c3 != 0.f) { float2 v = xw2[(size_t)r3.x * 32 + lane]; acc.x += c3 * v.x; acc.y += c3 * v.y; }
        }
        for (; j < n; j++) {
            int4 r = srec[wq][j];
            float c = __int_as_float(r.z);
            if (c != 0.f) { float2 v = xw2[(size_t)r.x * 32 + lane]; acc.x += c * v.x; acc.y += c * v.y; }
        }
        __syncwarp();
    }
    return acc;
}

__global__ __launch_bounds__(256)
void k_agg2f(const float* __restrict__ xw, const float* __restrict__ b,
             const float* __restrict__ a, float* __restrict__ out) {
    __shared__ int4 srec[8][32];
    int wq   = threadIdx.x >> 5;
    int lane = threadIdx.x & 31;
    int node = blockIdx.x * 8 + wq;
    if (node >= HALF) return;

    const float2* xw2 = (const float2*)xw;
    float2 r1 = agg2_node(xw2, srec, wq, lane, node);
    float2 r2 = agg2_node(xw2, srec, wq, lane, node + HALF);

    float2 bb = ((const float2*)b)[lane];
    float2 aa = ((const float2*)a)[lane];
    r1.x += bb.x; r1.y += bb.y;
    r2.x += bb.x; r2.y += bb.y;
    r1.x = (r1.x >= 0.f) ? r1.x : aa.x * r1.x;
    r1.y = (r1.y >= 0.f) ? r1.y : aa.y * r1.y;
    r2.x = (r2.x >= 0.f) ? r2.x : aa.x * r2.x;
    r2.y = (r2.y >= 0.f) ? r2.y : aa.y * r2.y;
    float2 o = make_float2(0.5f * (r1.x + r2.x), 0.5f * (r1.y + r2.y));
    ((float2*)out)[(size_t)node * 32 + lane] = o;
}

// ---------------- launch ----------------
extern "C" void kernel_launch(void* const* d_in, const int* in_sizes, int n_in,
                              void* d_out, int out_size) {
    const float* x   = (const float*)d_in[0];
    const int*   ei  = (const int*)d_in[1];    // int32 (JAX x64 disabled)
    const float* ew  = (const float*)d_in[2];
    const int*   et  = (const int*)d_in[3];    // int32
    const float* W1  = (const float*)d_in[4];
    const float* b1  = (const float*)d_in[5];
    const float* a1  = (const float*)d_in[6];
    const float* W2  = (const float*)d_in[7];
    const float* b2  = (const float*)d_in[8];
    const float* a2  = (const float*)d_in[9];
    float* out = (float*)d_out;

    if (!g_s2) {
        cudaStreamCreateWithFlags(&g_s2, cudaStreamNonBlocking);
        cudaEventCreateWithFlags(&g_evFork, cudaEventDisableTiming);
        cudaEventCreateWithFlags(&g_evJoin, cudaEventDisableTiming);
    }

    float *xw1, *buf1, *xw2;
    cudaGetSymbolAddress((void**)&xw1,  g_xw1);
    cudaGetSymbolAddress((void**)&buf1, g_buf1);
    cudaGetSymbolAddress((void**)&xw2,  g_xw2);

    const int nodeGrid = (NN + 255) / 256;
    const int edgeGrid = (NE + 255) / 256;
    const int aggGrid  = (NN + 7) / 8;
    const int agg2Grid = (HALF + 7) / 8;

    // ---- fork: GEMM1 on side stream, concurrent with the CSR build ----
    cudaEventRecord(g_evFork, 0);
    cudaStreamWaitEvent(g_s2, g_evFork, 0);
    k_gemm<CH1><<<(NN + 127) / 128, 256, 0, g_s2>>>(x, W1, xw1, NN);
    cudaEventRecord(g_evJoin, g_s2);

    // ---- CSR build + norm coefficients (default stream) ----
    k_init<<<nodeGrid, 256>>>();
    k_pass1<<<edgeGrid, 256>>>(ei, ew, et);
    k_scan1<<<NB1, 256>>>();
    k_scan2<<<1, 512>>>();
    k_scan3<<<NB1, 256>>>();
    k_reorder<<<edgeGrid, 256>>>(ei, ew, et);

    // ---- join: agg1 needs both xw1 (side stream) and CSR (default) ----
    cudaStreamWaitEvent(0, g_evJoin, 0);
    k_agg1<<<aggGrid, 256>>>(xw1, b1, a1, buf1);

    // layer 2
    k_gemm<CH2><<<(NN + 255) / 256, 256>>>(buf1, W2, xw2, NN);
    k_agg2f<<<agg2Grid, 256>>>(xw2, b2, a2, out);
}

// round 16
// speedup vs baseline: 1.5833x; 1.0632x over previous
#include <cuda_runtime.h>
#include <cuda_fp16.h>
#include <cstdint>

#define NN   100000
#define NE   1600000
#define CIN  128
#define CH1  128
#define CH2  64
#define HALF (NN/2)
#define NB1  ((NN + 255) / 256)     // 391 scan blocks

// ---------------- scratch (static device globals; no allocs) ----------------
__device__ __align__(16) __half g_xw1h[(size_t)NN * CH1]; // x @ W1 (fp16 messages)
__device__ __align__(16) float g_buf1[(size_t)NN * CH1];  // h1 = prelu(agg1), fp32
__device__ __align__(16) float g_xw2[(size_t)NN * CH2];   // h1 @ W2, fp32
__device__ float          g_dinv1[NN];
__device__ float          g_dinv2[NN];
__device__ unsigned int   g_pk[NN];         // packed: cnt (low 16) | et_sum (high 16)
__device__ float          g_wsum[NN];       // sum of edge weights per dst
__device__ unsigned short g_kloc[NE];       // per-edge local index within its dst
__device__ int   g_rowptr[NN + 1];          // CSR row pointers
__device__ int   g_psum[NB1];               // block partial sums for scan
__device__ __align__(16) int4 g_rec[NE];    // {src, c1_bits, c2_bits, 0} sorted by dst

// ---------------- side stream + events: lazily created on first call ----------
static cudaStream_t g_s2     = nullptr;
static cudaEvent_t  g_evFork = nullptr;
static cudaEvent_t  g_evJoin = nullptr;

// ---------------- f32x2 packed math helpers ----------------
__device__ __forceinline__ unsigned long long pack2(float x, float y) {
    unsigned long long r;
    asm("mov.b64 %0, {%1, %2};" : "=l"(r) : "f"(x), "f"(y));
    return r;
}
__device__ __forceinline__ void ffma2(unsigned long long& d,
                                      unsigned long long a, unsigned long long b) {
    asm("fma.rn.f32x2 %0, %1, %2, %3;" : "=l"(d) : "l"(a), "l"(b), "l"(d));
}
__device__ __forceinline__ float2 unpack2(unsigned long long v) {
    float2 f;
    asm("mov.b64 {%0, %1}, %2;" : "=f"(f.x), "=f"(f.y) : "l"(v));
    return f;
}

// ---------------- prep: init / histogram ----------------
__global__ __launch_bounds__(256) void k_init() {
    int i = blockIdx.x * 256 + threadIdx.x;
    if (i < NN) { g_pk[i] = 0u; g_wsum[i] = 0.f; }
}

__global__ __launch_bounds__(256) void k_pass1(const int* __restrict__ ei,
                                               const float* __restrict__ w,
                                               const int* __restrict__ et) {
    int e = blockIdx.x * 256 + threadIdx.x;
    if (e >= NE) return;
    int d = ei[NE + e];
    unsigned old = atomicAdd(&g_pk[d], 1u | ((unsigned)et[e] << 16));
    g_kloc[e] = (unsigned short)(old & 0xFFFFu);   // local index within dst
    atomicAdd(&g_wsum[d], w[e]);
}

// ---------------- 3-kernel exclusive scan of counts -> g_rowptr ----------------
__global__ __launch_bounds__(256) void k_scan1() {
    __shared__ int s[256];
    int tid = threadIdx.x;
    int i = blockIdx.x * 256 + tid;
    int v = (i < NN) ? (int)(g_pk[i] & 0xFFFFu) : 0;
    s[tid] = v;
    __syncthreads();
    for (int off = 1; off < 256; off <<= 1) {
        int t = (tid >= off) ? s[tid - off] : 0;
        __syncthreads();
        s[tid] += t;
        __syncthreads();
    }
    if (i < NN) g_rowptr[i] = s[tid] - v;   // block-local exclusive
    if (tid == 255) g_psum[blockIdx.x] = s[255];
}

__global__ __launch_bounds__(512) void k_scan2() {
    __shared__ int s[512];
    int tid = threadIdx.x;
    int v = (tid < NB1) ? g_psum[tid] : 0;
    s[tid] = v;
    __syncthreads();
    for (int off = 1; off < 512; off <<= 1) {
        int t = (tid >= off) ? s[tid - off] : 0;
        __syncthreads();
        s[tid] += t;
        __syncthreads();
    }
    if (tid < NB1) g_psum[tid] = s[tid] - v;   // exclusive over blocks
}

__global__ __launch_bounds__(256) void k_scan3() {      // + fused rsqrt of degrees
    int i = blockIdx.x * 256 + threadIdx.x;
    if (i < NN) {
        g_rowptr[i] += g_psum[blockIdx.x];
        g_dinv1[i] = rsqrtf(g_wsum[i] + 1.0f);                    // + self loop
        g_dinv2[i] = rsqrtf((float)(g_pk[i] >> 16) + 1.0f);
    }
    if (i == 0) g_rowptr[NN] = NE;
}

// ---------------- reorder edges into dst-sorted records (NO atomics) --------
__global__ __launch_bounds__(256) void k_reorder(const int* __restrict__ ei,
                                                 const float* __restrict__ w,
                                                 const int* __restrict__ et) {
    int e = blockIdx.x * 256 + threadIdx.x;
    if (e >= NE) return;
    int s = ei[e];
    int d = ei[NE + e];
    int pos = g_rowptr[d] + (int)g_kloc[e];
    float c1 = g_dinv1[s] * w[e] * g_dinv1[d];
    float c2 = g_dinv2[s] * (float)et[e] * g_dinv2[d];
    g_rec[pos] = make_int4(s, __float_as_int(c1), __float_as_int(c2), 0);
}

// ---------------- GEMM: Y[nrows,COUT] = X[nrows,CIN] @ W[CIN,COUT] ----------------
// HALF_OUT: emit __half (packed uint4 per 8 cols) instead of fp32.
template<int COUT, bool HALF_OUT>
__global__ __launch_bounds__(256)
void k_gemm(const float* __restrict__ X, const float* __restrict__ W,
            void* __restrict__ Y, int nrows) {
    constexpr int TC = 8, TR = 8, KC = 32;
    constexpr int CG = COUT / TC;
    constexpr int RG = 256 / CG;
    constexpr int RT = RG * TR;
    __shared__ float sX[RT][KC];
    __shared__ float sW[KC][COUT];

    int tid = threadIdx.x;
    int tx = tid % CG, ty = tid / CG;
    int r0base = blockIdx.x * RT;
    int r0 = ty * TR;

    unsigned long long acc[TR][4];
    #pragma unroll
    for (int j = 0; j < TR; j++) {
        acc[j][0] = 0ULL; acc[j][1] = 0ULL; acc[j][2] = 0ULL; acc[j][3] = 0ULL;
    }

    for (int k0 = 0; k0 < CIN; k0 += KC) {
        #pragma unroll
        for (int idx = tid; idx < RT * (KC / 4); idx += 256) {
            int row = idx / (KC / 4);
            int kq  = idx % (KC / 4);
            int grow = r0base + row;
            float4 v = (grow < nrows)
                ? ((const float4*)(X + (size_t)grow * CIN + k0))[kq]
                : make_float4(0.f, 0.f, 0.f, 0.f);
            *(float4*)&sX[row][kq * 4] = v;
        }
        #pragma unroll
        for (int idx = tid; idx < KC * (COUT / 4); idx += 256) {
            int kk = idx / (COUT / 4);
            int cq = idx % (COUT / 4);
            *(float4*)&sW[kk][cq * 4] = ((const float4*)(W + (size_t)(k0 + kk) * COUT))[cq];
        }
        __syncthreads();

        #pragma unroll 4
        for (int kk = 0; kk < KC; kk++) {
            ulonglong2 w01 = *(const ulonglong2*)&sW[kk][tx * TC];
            ulonglong2 w23 = *(const ulonglong2*)&sW[kk][tx * TC + 4];
            #pragma unroll
            for (int j = 0; j < TR; j++) {
                float xv = sX[r0 + j][kk];
                unsigned long long xx = pack2(xv, xv);
                ffma2(acc[j][0], xx, w01.x);
                ffma2(acc[j][1], xx, w01.y);
                ffma2(acc[j][2], xx, w23.x);
                ffma2(acc[j][3], xx, w23.y);
            }
        }
        __syncthreads();
    }

    #pragma unroll
    for (int j = 0; j < TR; j++) {
        int grow = r0base + r0 + j;
        if (grow < nrows) {
            float2 p0 = unpack2(acc[j][0]);
            float2 p1 = unpack2(acc[j][1]);
            float2 p2 = unpack2(acc[j][2]);
            float2 p3 = unpack2(acc[j][3]);
            if (HALF_OUT) {
                __half2 h0 = __floats2half2_rn(p0.x, p0.y);
                __half2 h1 = __floats2half2_rn(p1.x, p1.y);
                __half2 h2 = __floats2half2_rn(p2.x, p2.y);
                __half2 h3 = __floats2half2_rn(p3.x, p3.y);
                uint4 pk = make_uint4(*(unsigned*)&h0, *(unsigned*)&h1,
                                      *(unsigned*)&h2, *(unsigned*)&h3);
                *(uint4*)((__half*)Y + (size_t)grow * COUT + tx * TC) = pk;
            } else {
                float4* yp = (float4*)((float*)Y + (size_t)grow * COUT + tx * TC);
                yp[0] = make_float4(p0.x, p0.y, p1.x, p1.y);
                yp[1] = make_float4(p2.x, p2.y, p3.x, p3.y);
            }
        }
    }
}

// ---------------- layer-1 aggregation: warp per dst, fp16 gathers ----------------
// lane owns 4 channels; gathers uint2 = 4 halves (256 B per edge across warp)
__device__ __forceinline__ float4 h4_to_f4(uint2 raw) {
    __half2 a = *(__half2*)&raw.x;
    __half2 b = *(__half2*)&raw.y;
    float2 fa = __half22float2(a);
    float2 fb = __half22float2(b);
    return make_float4(fa.x, fa.y, fb.x, fb.y);
}

__global__ __launch_bounds__(256)
void k_agg1(const __half* __restrict__ xwh, const float* __restrict__ b,
            const float* __restrict__ a, float* __restrict__ outbuf) {
    __shared__ int4 srec[8][32];
    int wq   = threadIdx.x >> 5;
    int lane = threadIdx.x & 31;
    int dst  = blockIdx.x * 8 + wq;
    if (dst >= NN) return;

    const uint2* xwh2 = (const uint2*)xwh;     // 32 uint2 per row (128 halves)
    float dv = g_dinv1[dst];
    float4 acc = h4_to_f4(xwh2[(size_t)dst * 32 + lane]);
    float sc = dv * dv;
    acc.x *= sc; acc.y *= sc; acc.z *= sc; acc.w *= sc;

    int start = g_rowptr[dst], end = g_rowptr[dst + 1];
    for (int base = start; base < end; base += 32) {
        int n = end - base; if (n > 32) n = 32;
        if (lane < n) srec[wq][lane] = g_rec[base + lane];
        __syncwarp();
        int j = 0;
        for (; j + 4 <= n; j += 4) {
            int4 r0 = srec[wq][j], r1 = srec[wq][j + 1];
            int4 r2 = srec[wq][j + 2], r3 = srec[wq][j + 3];
            float4 v0 = h4_to_f4(xwh2[(size_t)r0.x * 32 + lane]);
            float4 v1 = h4_to_f4(xwh2[(size_t)r1.x * 32 + lane]);
            float4 v2 = h4_to_f4(xwh2[(size_t)r2.x * 32 + lane]);
            float4 v3 = h4_to_f4(xwh2[(size_t)r3.x * 32 + lane]);
            float c0 = __int_as_float(r0.y), c1 = __int_as_float(r1.y);
            float c2 = __int_as_float(r2.y), c3 = __int_as_float(r3.y);
            acc.x += c0 * v0.x; acc.y += c0 * v0.y; acc.z += c0 * v0.z; acc.w += c0 * v0.w;
            acc.x += c1 * v1.x; acc.y += c1 * v1.y; acc.z += c1 * v1.z; acc.w += c1 * v1.w;
            acc.x += c2 * v2.x; acc.y += c2 * v2.y; acc.z += c2 * v2.z; acc.w += c2 * v2.w;
            acc.x += c3 * v3.x; acc.y += c3 * v3.y; acc.z += c3 * v3.z; acc.w += c3 * v3.w;
        }
        for (; j < n; j++) {
            int4 r = srec[wq][j];
            float c = __int_as_float(r.y);
            float4 v = h4_to_f4(xwh2[(size_t)r.x * 32 + lane]);
            acc.x += c * v.x; acc.y += c * v.y; acc.z += c * v.z; acc.w += c * v.w;
        }
        __syncwarp();
    }

    float4 bb = ((const float4*)b)[lane];
    float4 aa = ((const float4*)a)[lane];
    acc.x += bb.x; acc.y += bb.y; acc.z += bb.z; acc.w += bb.w;
    acc.x = (acc.x >= 0.f) ? acc.x : aa.x * acc.x;
    acc.y = (acc.y >= 0.f) ? acc.y : aa.y * acc.y;
    acc.z = (acc.z >= 0.f) ? acc.z : aa.z * acc.z;
    acc.w = (acc.w >= 0.f) ? acc.w : aa.w * acc.w;
    ((float4*)outbuf)[(size_t)dst * 32 + lane] = acc;
}

// ---------------- layer-2 aggregation fused with epilogue (fp32) ----------------
__device__ __forceinline__ float2 agg2_node(const float2* __restrict__ xw2,
                                            int4 (*srec)[32], int wq, int lane,
                                            int dst) {
    float dv = g_dinv2[dst];
    float2 acc = xw2[(size_t)dst * 32 + lane];
    float sc = dv * dv;
    acc.x *= sc; acc.y *= sc;

    int start = g_rowptr[dst], end = g_rowptr[dst + 1];
    for (int base = start; base < end; base += 32) {
        int n = end - base; if (n > 32) n = 32;
        if (lane < n) srec[wq][lane] = g_rec[base + lane];
        __syncwarp();
        int j = 0;
        for (; j + 4 <= n; j += 4) {
            int4 r0 = srec[wq][j], r1 = srec[wq][j + 1];
            int4 r2 = srec[wq][j + 2], r3 = srec[wq][j + 3];
            float c0 = __int_as_float(r0.z), c1 = __int_as_float(r1.z);
            float c2 = __int_as_float(r2.z), c3 = __int_as_float(r3.z);
            if (c0 != 0.f) { float2 v = xw2[(size_t)r0.x * 32 + lane]; acc.x += c0 * v.x; acc.y += c0 * v.y; }
            if (c1 != 0.f) { float2 v = xw2[(size_t)r1.x * 32 + lane]; acc.x += c1 * v.x; acc.y += c1 * v.y; }
            if (c2 != 0.f) { float2 v = xw2[(size_t)r2.x * 32 + lane]; acc.x += c2 * v.x; acc.y += c2 * v.y; }
            if (c3 != 0.f) { float2 v = xw2[(size_t)r3.x * 32 + lane]; acc.x += c3 * v.x; acc.y += c3 * v.y; }
        }
        for (; j < n; j++) {
            int4 r = srec[wq][j];
            float c = __int_as_float(r.z);
            if (c != 0.f) { float2 v = xw2[(size_t)r.x * 32 + lane]; acc.x += c * v.x; acc.y += c * v.y; }
        }
        __syncwarp();
    }
    return acc;
}

__global__ __launch_bounds__(256)
void k_agg2f(const float* __restrict__ xw, const float* __restrict__ b,
             const float* __restrict__ a, float* __restrict__ out) {
    __shared__ int4 srec[8][32];
    int wq   = threadIdx.x >> 5;
    int lane = threadIdx.x & 31;
    int node = blockIdx.x * 8 + wq;
    if (node >= HALF) return;

    const float2* xw2 = (const float2*)xw;
    float2 r1 = agg2_node(xw2, srec, wq, lane, node);
    float2 r2 = agg2_node(xw2, srec, wq, lane, node + HALF);

    float2 bb = ((const float2*)b)[lane];
    float2 aa = ((const float2*)a)[lane];
    r1.x += bb.x; r1.y += bb.y;
    r2.x += bb.x; r2.y += bb.y;
    r1.x = (r1.x >= 0.f) ? r1.x : aa.x * r1.x;
    r1.y = (r1.y >= 0.f) ? r1.y : aa.y * r1.y;
    r2.x = (r2.x >= 0.f) ? r2.x : aa.x * r2.x;
    r2.y = (r2.y >= 0.f) ? r2.y : aa.y * r2.y;
    float2 o = make_float2(0.5f * (r1.x + r2.x), 0.5f * (r1.y + r2.y));
    ((float2*)out)[(size_t)node * 32 + lane] = o;
}

// ---------------- launch ----------------
extern "C" void kernel_launch(void* const* d_in, const int* in_sizes, int n_in,
                              void* d_out, int out_size) {
    const float* x   = (const float*)d_in[0];
    const int*   ei  = (const int*)d_in[1];    // int32 (JAX x64 disabled)
    const float* ew  = (const float*)d_in[2];
    const int*   et  = (const int*)d_in[3];    // int32
    const float* W1  = (const float*)d_in[4];
    const float* b1  = (const float*)d_in[5];
    const float* a1  = (const float*)d_in[6];
    const float* W2  = (const float*)d_in[7];
    const float* b2  = (const float*)d_in[8];
    const float* a2  = (const float*)d_in[9];
    float* out = (float*)d_out;

    if (!g_s2) {
        cudaStreamCreateWithFlags(&g_s2, cudaStreamNonBlocking);
        cudaEventCreateWithFlags(&g_evFork, cudaEventDisableTiming);
        cudaEventCreateWithFlags(&g_evJoin, cudaEventDisableTiming);
    }

    __half* xw1h;  float *buf1, *xw2;
    cudaGetSymbolAddress((void**)&xw1h, g_xw1h);
    cudaGetSymbolAddress((void**)&buf1, g_buf1);
    cudaGetSymbolAddress((void**)&xw2,  g_xw2);

    const int nodeGrid = (NN + 255) / 256;
    const int edgeGrid = (NE + 255) / 256;
    const int aggGrid  = (NN + 7) / 8;
    const int agg2Grid = (HALF + 7) / 8;

    // ---- fork: GEMM1 (fp16 out) on side stream, concurrent with CSR build ----
    cudaEventRecord(g_evFork, 0);
    cudaStreamWaitEvent(g_s2, g_evFork, 0);
    k_gemm<CH1, true><<<(NN + 127) / 128, 256, 0, g_s2>>>(x, W1, xw1h, NN);
    cudaEventRecord(g_evJoin, g_s2);

    // ---- CSR build + norm coefficients (default stream) ----
    k_init<<<nodeGrid, 256>>>();
    k_pass1<<<edgeGrid, 256>>>(ei, ew, et);
    k_scan1<<<NB1, 256>>>();
    k_scan2<<<1, 512>>>();
    k_scan3<<<NB1, 256>>>();
    k_reorder<<<edgeGrid, 256>>>(ei, ew, et);

    // ---- join: agg1 needs both xw1h (side stream) and CSR (default) ----
    cudaStreamWaitEvent(0, g_evJoin, 0);
    k_agg1<<<aggGrid, 256>>>(xw1h, b1, a1, buf1);

    // layer 2 (fp32 throughout)
    k_gemm<CH2, false><<<(NN + 255) / 256, 256>>>(buf1, W2, xw2, NN);
    k_agg2f<<<agg2Grid, 256>>>(xw2, b2, a2, out);
}